// round 12
// baseline (speedup 1.0000x reference)
#include <cuda_runtime.h>
#include <cuda_fp16.h>
#include <math.h>

#define BB 64
#define TT 2048
#define HH 256
#define CH 128
#define NCHUNK 16              // TT / CH
#define NBLK (BB * NCHUNK)     // 1024
#define FAN_EPS 1e-4f

// Compile-time caps: 1e4 / sqrt(w-1)
#define CAP5  (1.0e4f / 2.0f)
#define CAP10 (1.0e4f / 3.0f)
#define CAP20 (1.0e4f / 4.35889894354067f)

// Transposed partial layout: [slice][h][blk] -> coalesced reduction reads.
__device__ float g_psum[2][HH][NBLK];
__device__ float g_psumsq[2][HH][NBLK];
__device__ float g_cA[2][HH];   // gamma/sd per slice
__device__ float g_cB[2][HH];   // beta - mu*gamma/sd per slice

// Materialized FAN output, t-paired fp16: word (tp, h) = (f[2tp,h], f[2tp+1,h]).
__device__ __half2 g_fpk[(size_t)BB * (TT / 2) * HH];

// mu and pre-scale clamped inverse-sd from UNSCALED variance varp = s2 - s1*mu:
//   r = min(rsqrt(varp), CAP) with CAP = 1e4/sqrt(w-1)  [immediate]
//   caller multiplies by alk = al*sqrt(w-1): exactly min(rsqrt(var),1e4)*al.
// No fmax(varp,0): varp<0 -> rsqrt=NaN -> fminf(NaN,CAP)=CAP; exact FMA
// cancellation yields +0 -> rsqrt=+inf -> CAP. Identical to the clamp.
__device__ __forceinline__ void wstat(float s1, float s2, float invw, float cap,
                                      float& mu, float& r) {
    mu = s1 * invw;
    float varp = fmaf(-s1, mu, s2);
    r = fminf(rsqrtf(varp), cap);
}

template <bool EDGE>
__device__ __forceinline__ void process_chunk(
    const float* __restrict__ px, __half2* __restrict__ pf, int t0,
    float alk5, float alk10, float alk20, float& accS, float& accQ)
{
    float hist[32];
    float s1_5 = 0, s2_5 = 0, s1_10 = 0, s2_10 = 0, s1_20 = 0, s2_20 = 0;
    float fmu5 = 0, fr5 = 0, fmu10 = 0, fr10 = 0, fmu20 = 0, fr20 = 0;

    if (EDGE) {
        // chunk 0: ring starts zeroed; first-full-window stats for edge pad.
#pragma unroll
        for (int j = 0; j < 32; j++) hist[j] = 0.0f;
        float s1 = 0, s2 = 0;
#pragma unroll
        for (int j = 0; j < 20; j++) {
            float v = px[j * HH];
            s1 += v; s2 = fmaf(v, v, s2);
            if (j == 4)  wstat(s1, s2, 0.2f,  CAP5,  fmu5,  fr5);
            if (j == 9)  wstat(s1, s2, 0.1f,  CAP10, fmu10, fr10);
            if (j == 19) wstat(s1, s2, 0.05f, CAP20, fmu20, fr20);
        }
    } else {
        // preload halo x[t0-32 .. t0-1]; t0 % 32 == 0 keeps ring phase aligned.
#pragma unroll
        for (int j = 0; j < 32; j++) hist[j] = px[(t0 - 32 + j) * HH];
#pragma unroll
        for (int j = 12; j < 32; j++) {
            float v = hist[j];
            s1_20 += v; s2_20 = fmaf(v, v, s2_20);
            if (j >= 22) { s1_10 += v; s2_10 = fmaf(v, v, s2_10); }
            if (j >= 27) { s1_5  += v; s2_5  = fmaf(v, v, s2_5);  }
        }
    }

    const float* p = px + (size_t)t0 * HH;
    __half2* pw = pf + (size_t)(t0 / 2) * HH;   // pair-row base

#pragma unroll 1
    for (int base = 0; base < CH; base += 32) {
        float fprev = 0.0f;
#pragma unroll
        for (int u = 0; u < 32; ++u) {
            float xt  = p[u * HH];
            float x5  = hist[(u + 27) & 31];
            float x10 = hist[(u + 22) & 31];
            float x20 = hist[(u + 12) & 31];
            hist[u] = xt;
            // s1 += (xt-xw); s2 += (xt-xw)*(xt+xw)
            {
                float d = xt - x5,  q = xt + x5;
                s1_5  += d;  s2_5  = fmaf(d, q, s2_5);
            }
            {
                float d = xt - x10, q = xt + x10;
                s1_10 += d;  s2_10 = fmaf(d, q, s2_10);
            }
            {
                float d = xt - x20, q = xt + x20;
                s1_20 += d;  s2_20 = fmaf(d, q, s2_20);
            }

            float mu5, r5, mu10, r10, mu20, r20;
            wstat(s1_5,  s2_5,  0.2f,  CAP5,  mu5,  r5);
            wstat(s1_10, s2_10, 0.1f,  CAP10, mu10, r10);
            wstat(s1_20, s2_20, 0.05f, CAP20, mu20, r20);

            if (EDGE) {
                int t = base + u;          // t0 == 0 here
                if (t < 4)  { mu5  = fmu5;  r5  = fr5;  }
                if (t < 9)  { mu10 = fmu10; r10 = fr10; }
                if (t < 19) { mu20 = fmu20; r20 = fr20; }
            }

            float w5 = r5 * alk5, w10 = r10 * alk10, w20 = r20 * alk20;
            float wsum = (w5 + w10) + w20;
            float msum = fmaf(mu20, w20, fmaf(mu10, w10, mu5 * w5));
            float f = fmaf(xt, wsum, -msum);

            if ((u & 1) == 0) {
                fprev = f;
            } else {
                // one packed cvt + one STG.32 per t-pair
                pw[(u >> 1) * HH] = __floats2half2_rn(fprev, f);
            }
            accS += f;
            accQ = fmaf(f, f, accQ);
        }
        p  += 32 * HH;
        pw += 16 * HH;
    }
}

__global__ __launch_bounds__(HH, 4)
void fan_kernel(const float* __restrict__ x, const float* __restrict__ alpha) {
    const int c  = blockIdx.x & (NCHUNK - 1);
    const int b  = blockIdx.x >> 4;
    const int h  = threadIdx.x;
    const int t0 = c * CH;
    const float* px = x + ((size_t)b * TT) * HH + h;
    __half2* pf = g_fpk + ((size_t)b * (TT / 2)) * HH + h;

    // softmax over the 3 window weights; fold sqrt(w-1) in (3 live constants).
    float alk5, alk10, alk20;
    {
        float a0 = alpha[h * 3 + 0], a1 = alpha[h * 3 + 1], a2 = alpha[h * 3 + 2];
        float mx = fmaxf(a0, fmaxf(a1, a2));
        float e0 = expf(a0 - mx), e1 = expf(a1 - mx), e2 = expf(a2 - mx);
        float inv = 1.0f / (e0 + e1 + e2);
        alk5  = e0 * inv * 2.0f;              // sqrt(4)
        alk10 = e1 * inv * 3.0f;              // sqrt(9)
        alk20 = e2 * inv * 4.35889894354067f; // sqrt(19)
    }

    float accS = 0.0f, accQ = 0.0f;
    if (c == 0)
        process_chunk<true >(px, pf, t0, alk5, alk10, alk20, accS, accQ);
    else
        process_chunk<false>(px, pf, t0, alk5, alk10, alk20, accS, accQ);

    const int blk = blockIdx.x;
    const bool in0 = (c < 12);   // t < 1536
    const bool in1 = (c >= 8);   // t >= 1024
    g_psum[0][h][blk]   = in0 ? accS : 0.0f;
    g_psumsq[0][h][blk] = in0 ? accQ : 0.0f;
    g_psum[1][h][blk]   = in1 ? accS : 0.0f;
    g_psumsq[1][h][blk] = in1 ? accQ : 0.0f;
}

// One block per (slice, h): 256 threads tree-reduce the 1024 partials.
__global__ __launch_bounds__(256)
void stats_kernel(const float* __restrict__ gamma, const float* __restrict__ beta) {
    const int s = blockIdx.x >> 8;
    const int h = blockIdx.x & (HH - 1);
    const int tid = threadIdx.x;

    double dS = 0.0, dQ = 0.0;
#pragma unroll
    for (int i = 0; i < NBLK / 256; ++i) {
        dS += (double)g_psum[s][h][tid + i * 256];
        dQ += (double)g_psumsq[s][h][tid + i * 256];
    }
    __shared__ double shS[256], shQ[256];
    shS[tid] = dS; shQ[tid] = dQ;
    __syncthreads();
    for (int off = 128; off > 0; off >>= 1) {
        if (tid < off) { shS[tid] += shS[tid + off]; shQ[tid] += shQ[tid + off]; }
        __syncthreads();
    }
    if (tid == 0) {
        double S = shS[0], Q = shQ[0];
        const double n = (s == 0) ? (double)BB * 1536.0 : (double)BB * 1024.0;
        double mu  = S / n;
        double var = (Q - S * S / n) / (n - 1.0);
        if (var < 0.0) var = 0.0;
        double sd = sqrt(var);
        if (sd < 1e-4) sd = 1e-4;
        float g  = gamma[s * HH + h];
        float be = beta[s * HH + h];
        float a  = (float)((double)g / sd);
        g_cA[s][h] = a;
        g_cB[s][h] = be - (float)mu * a;
    }
}

// Streaming apply: out = x + cAr*f + cBr, region-folded coefficients.
// grid = NBLK (same (b, chunk) mapping), block = 256.
// Thread layout: 64 h-groups x 4 pair-rows in flight; each thread handles a
// t-pair x 4 channels per iter: 16B f16 + 2x16B x reads, 2x16B out writes.
// All accesses use streaming hints (single-use data).
__global__ __launch_bounds__(256)
void apply_kernel(const float* __restrict__ x, float* __restrict__ out) {
    const int c   = blockIdx.x & (NCHUNK - 1);
    const int b   = blockIdx.x >> 4;
    const int tid = threadIdx.x;
    const int hg  = tid & 63;        // h-group: channels 4*hg .. 4*hg+3
    const int r0  = tid >> 6;        // pair-row offset 0..3

    // Region is uniform per chunk (boundaries 1024/1536 multiples of CH).
    const float inv1 = 1.0f / (1.0f + FAN_EPS);
    const float inv2 = 1.0f / (2.0f + FAN_EPS);
    float A[4], B[4];
#pragma unroll
    for (int j = 0; j < 4; ++j) {
        int h = 4 * hg + j;
        float A0 = g_cA[0][h], B0 = g_cB[0][h];
        float A1 = g_cA[1][h], B1 = g_cB[1][h];
        if (c < 8)       { A[j] = A0 * inv1;        B[j] = B0 * inv1; }
        else if (c < 12) { A[j] = (A0 + A1) * inv2; B[j] = (B0 + B1) * inv2; }
        else             { A[j] = A1 * inv1;        B[j] = B1 * inv1; }
    }

    const size_t chunk_base = ((size_t)b * TT + (size_t)c * CH) * HH;
    const float4* __restrict__ x4 = (const float4*)(x + chunk_base);
    float4* __restrict__ o4 = (float4*)(out + chunk_base);
    // pair-row base into the packed f16 buffer
    const uint4* __restrict__ f4 = (const uint4*)
        (g_fpk + ((size_t)b * (TT / 2) + (size_t)c * (CH / 2)) * HH);

#pragma unroll 8
    for (int it = 0; it < CH / 8; ++it) {
        int pr = it * 4 + r0;                       // pair-row 0..63
        // f packed: 4 channels x 2 t's = 4 uint32 = 16B
        uint4 fw = __ldcs(&f4[(size_t)pr * (HH / 4) + hg]);
        float2 f0a = __half22float2(*(const __half2*)&fw.x);  // (t0, t1) ch j=0
        float2 f1a = __half22float2(*(const __half2*)&fw.y);
        float2 f2a = __half22float2(*(const __half2*)&fw.z);
        float2 f3a = __half22float2(*(const __half2*)&fw.w);

        size_t vi0 = (size_t)(2 * pr) * (HH / 4) + hg;
        float4 xv0 = __ldcs(&x4[vi0]);
        float4 xv1 = __ldcs(&x4[vi0 + (HH / 4)]);

        float4 ov0, ov1;
        ov0.x = fmaf(f0a.x, A[0], xv0.x) + B[0];
        ov0.y = fmaf(f1a.x, A[1], xv0.y) + B[1];
        ov0.z = fmaf(f2a.x, A[2], xv0.z) + B[2];
        ov0.w = fmaf(f3a.x, A[3], xv0.w) + B[3];
        ov1.x = fmaf(f0a.y, A[0], xv1.x) + B[0];
        ov1.y = fmaf(f1a.y, A[1], xv1.y) + B[1];
        ov1.z = fmaf(f2a.y, A[2], xv1.z) + B[2];
        ov1.w = fmaf(f3a.y, A[3], xv1.w) + B[3];
        __stcs(&o4[vi0], ov0);
        __stcs(&o4[vi0 + (HH / 4)], ov1);
    }
}

extern "C" void kernel_launch(void* const* d_in, const int* in_sizes, int n_in,
                              void* d_out, int out_size) {
    (void)in_sizes; (void)n_in; (void)out_size;
    const float* x     = (const float*)d_in[0];
    const float* alpha = (const float*)d_in[1];
    const float* gamma = (const float*)d_in[2];
    const float* beta  = (const float*)d_in[3];
    float* out = (float*)d_out;

    fan_kernel<<<NBLK, HH>>>(x, alpha);
    stats_kernel<<<2 * HH, 256>>>(gamma, beta);
    apply_kernel<<<NBLK, 256>>>(x, out);
}

// round 14
// speedup vs baseline: 1.3377x; 1.3377x over previous
#include <cuda_runtime.h>
#include <cuda_fp16.h>
#include <math.h>

#define BB 64
#define TT 2048
#define HH 256
#define CH 128
#define NCHUNK 16              // TT / CH
#define NBLK (BB * NCHUNK)     // 1024
#define FAN_EPS 1e-4f

// Compile-time caps: 1e4 / sqrt(w-1)
#define CAP5  (1.0e4f / 2.0f)
#define CAP10 (1.0e4f / 3.0f)
#define CAP20 (1.0e4f / 4.35889894354067f)

// Transposed partial layout: [slice][h][blk] -> coalesced reduction reads.
__device__ float g_psum[2][HH][NBLK];
__device__ float g_psumsq[2][HH][NBLK];
__device__ float g_cA[2][HH];   // gamma/sd per slice
__device__ float g_cB[2][HH];   // beta - mu*gamma/sd per slice

// Materialized FAN output (fp16). 64MB static scratch.
__device__ __half g_f16[(size_t)BB * TT * HH];

// mu and pre-scale clamped inverse-sd from UNSCALED variance varp = s2 - s1*mu:
//   r = min(rsqrt(varp), CAP) with CAP = 1e4/sqrt(w-1)  [immediate]
//   caller multiplies by alk = al*sqrt(w-1): exactly min(rsqrt(var),1e4)*al.
// No fmax(varp,0): varp<0 -> rsqrt=NaN -> fminf(NaN,CAP)=CAP; exact FMA
// cancellation yields +0 -> rsqrt=+inf -> CAP. Identical to the clamp.
__device__ __forceinline__ void wstat(float s1, float s2, float invw, float cap,
                                      float& mu, float& r) {
    mu = s1 * invw;
    float varp = fmaf(-s1, mu, s2);
    r = fminf(rsqrtf(varp), cap);
}

template <bool EDGE>
__device__ __forceinline__ void process_chunk(
    const float* __restrict__ px, __half* __restrict__ pf, int t0,
    float alk5, float alk10, float alk20, float& accS, float& accQ)
{
    float hist[32];
    float s1_5 = 0, s2_5 = 0, s1_10 = 0, s2_10 = 0, s1_20 = 0, s2_20 = 0;
    float fmu5 = 0, fr5 = 0, fmu10 = 0, fr10 = 0, fmu20 = 0, fr20 = 0;

    if (EDGE) {
        // chunk 0: ring starts zeroed; first-full-window stats for edge pad.
#pragma unroll
        for (int j = 0; j < 32; j++) hist[j] = 0.0f;
        float s1 = 0, s2 = 0;
#pragma unroll
        for (int j = 0; j < 20; j++) {
            float v = px[j * HH];
            s1 += v; s2 = fmaf(v, v, s2);
            if (j == 4)  wstat(s1, s2, 0.2f,  CAP5,  fmu5,  fr5);
            if (j == 9)  wstat(s1, s2, 0.1f,  CAP10, fmu10, fr10);
            if (j == 19) wstat(s1, s2, 0.05f, CAP20, fmu20, fr20);
        }
    } else {
        // preload halo x[t0-32 .. t0-1]; t0 % 32 == 0 keeps ring phase aligned.
#pragma unroll
        for (int j = 0; j < 32; j++) hist[j] = px[(t0 - 32 + j) * HH];
#pragma unroll
        for (int j = 12; j < 32; j++) {
            float v = hist[j];
            s1_20 += v; s2_20 = fmaf(v, v, s2_20);
            if (j >= 22) { s1_10 += v; s2_10 = fmaf(v, v, s2_10); }
            if (j >= 27) { s1_5  += v; s2_5  = fmaf(v, v, s2_5);  }
        }
    }

    const float* p = px + (size_t)t0 * HH;
    __half* pw = pf + (size_t)t0 * HH;

#pragma unroll 1
    for (int base = 0; base < CH; base += 32) {
#pragma unroll
        for (int u = 0; u < 32; ++u) {
            float xt  = p[u * HH];
            float x5  = hist[(u + 27) & 31];
            float x10 = hist[(u + 22) & 31];
            float x20 = hist[(u + 12) & 31];
            hist[u] = xt;
            // s1 += (xt-xw); s2 += (xt-xw)*(xt+xw)
            {
                float d = xt - x5,  q = xt + x5;
                s1_5  += d;  s2_5  = fmaf(d, q, s2_5);
            }
            {
                float d = xt - x10, q = xt + x10;
                s1_10 += d;  s2_10 = fmaf(d, q, s2_10);
            }
            {
                float d = xt - x20, q = xt + x20;
                s1_20 += d;  s2_20 = fmaf(d, q, s2_20);
            }

            float mu5, r5, mu10, r10, mu20, r20;
            wstat(s1_5,  s2_5,  0.2f,  CAP5,  mu5,  r5);
            wstat(s1_10, s2_10, 0.1f,  CAP10, mu10, r10);
            wstat(s1_20, s2_20, 0.05f, CAP20, mu20, r20);

            if (EDGE) {
                int t = base + u;          // t0 == 0 here
                if (t < 4)  { mu5  = fmu5;  r5  = fr5;  }
                if (t < 9)  { mu10 = fmu10; r10 = fr10; }
                if (t < 19) { mu20 = fmu20; r20 = fr20; }
            }

            float w5 = r5 * alk5, w10 = r10 * alk10, w20 = r20 * alk20;
            float wsum = (w5 + w10) + w20;
            float msum = fmaf(mu20, w20, fmaf(mu10, w10, mu5 * w5));
            float f = fmaf(xt, wsum, -msum);

            pw[u * HH] = __float2half_rn(f);
            accS += f;
            accQ = fmaf(f, f, accQ);
        }
        p  += 32 * HH;
        pw += 32 * HH;
    }
}

__global__ __launch_bounds__(HH, 4)
void fan_kernel(const float* __restrict__ x, const float* __restrict__ alpha) {
    const int c  = blockIdx.x & (NCHUNK - 1);
    const int b  = blockIdx.x >> 4;
    const int h  = threadIdx.x;
    const int t0 = c * CH;
    const float* px = x + ((size_t)b * TT) * HH + h;
    __half* pf = g_f16 + ((size_t)b * TT) * HH + h;

    // softmax over the 3 window weights; fold sqrt(w-1) in (3 live constants).
    float alk5, alk10, alk20;
    {
        float a0 = alpha[h * 3 + 0], a1 = alpha[h * 3 + 1], a2 = alpha[h * 3 + 2];
        float mx = fmaxf(a0, fmaxf(a1, a2));
        float e0 = expf(a0 - mx), e1 = expf(a1 - mx), e2 = expf(a2 - mx);
        float inv = 1.0f / (e0 + e1 + e2);
        alk5  = e0 * inv * 2.0f;              // sqrt(4)
        alk10 = e1 * inv * 3.0f;              // sqrt(9)
        alk20 = e2 * inv * 4.35889894354067f; // sqrt(19)
    }

    float accS = 0.0f, accQ = 0.0f;
    if (c == 0)
        process_chunk<true >(px, pf, t0, alk5, alk10, alk20, accS, accQ);
    else
        process_chunk<false>(px, pf, t0, alk5, alk10, alk20, accS, accQ);

    const int blk = blockIdx.x;
    const bool in0 = (c < 12);   // t < 1536
    const bool in1 = (c >= 8);   // t >= 1024
    g_psum[0][h][blk]   = in0 ? accS : 0.0f;
    g_psumsq[0][h][blk] = in0 ? accQ : 0.0f;
    g_psum[1][h][blk]   = in1 ? accS : 0.0f;
    g_psumsq[1][h][blk] = in1 ? accQ : 0.0f;
}

// One block per (slice, h): 256 threads tree-reduce the 1024 partials.
__global__ __launch_bounds__(256)
void stats_kernel(const float* __restrict__ gamma, const float* __restrict__ beta) {
    const int s = blockIdx.x >> 8;
    const int h = blockIdx.x & (HH - 1);
    const int tid = threadIdx.x;

    double dS = 0.0, dQ = 0.0;
#pragma unroll
    for (int i = 0; i < NBLK / 256; ++i) {
        dS += (double)g_psum[s][h][tid + i * 256];
        dQ += (double)g_psumsq[s][h][tid + i * 256];
    }
    __shared__ double shS[256], shQ[256];
    shS[tid] = dS; shQ[tid] = dQ;
    __syncthreads();
    for (int off = 128; off > 0; off >>= 1) {
        if (tid < off) { shS[tid] += shS[tid + off]; shQ[tid] += shQ[tid + off]; }
        __syncthreads();
    }
    if (tid == 0) {
        double S = shS[0], Q = shQ[0];
        const double n = (s == 0) ? (double)BB * 1536.0 : (double)BB * 1024.0;
        double mu  = S / n;
        double var = (Q - S * S / n) / (n - 1.0);
        if (var < 0.0) var = 0.0;
        double sd = sqrt(var);
        if (sd < 1e-4) sd = 1e-4;
        float g  = gamma[s * HH + h];
        float be = beta[s * HH + h];
        float a  = (float)((double)g / sd);
        g_cA[s][h] = a;
        g_cB[s][h] = be - (float)mu * a;
    }
}

// Streaming apply: out = x + cAr*f + cBr, region-folded coefficients.
// grid = NBLK (same (b, chunk) mapping), block = 256.
// Thread layout: 64 h-groups x 4 row-pairs in flight; each thread handles
// 2 rows x 4 channels per iter. Loads use default policy (f is L2-hot from
// fan_kernel); stores use __stcs so out doesn't evict f from L2.
__global__ __launch_bounds__(256)
void apply_kernel(const float* __restrict__ x, float* __restrict__ out) {
    const int c   = blockIdx.x & (NCHUNK - 1);
    const int b   = blockIdx.x >> 4;
    const int tid = threadIdx.x;
    const int hg  = tid & 63;        // h-group: channels 4*hg .. 4*hg+3
    const int r0  = tid >> 6;        // row-pair offset 0..3

    // Region is uniform per chunk (boundaries 1024/1536 multiples of CH).
    const float inv1 = 1.0f / (1.0f + FAN_EPS);
    const float inv2 = 1.0f / (2.0f + FAN_EPS);
    float A[4], B[4];
#pragma unroll
    for (int j = 0; j < 4; ++j) {
        int h = 4 * hg + j;
        float A0 = g_cA[0][h], B0 = g_cB[0][h];
        float A1 = g_cA[1][h], B1 = g_cB[1][h];
        if (c < 8)       { A[j] = A0 * inv1;        B[j] = B0 * inv1; }
        else if (c < 12) { A[j] = (A0 + A1) * inv2; B[j] = (B0 + B1) * inv2; }
        else             { A[j] = A1 * inv1;        B[j] = B1 * inv1; }
    }

    const size_t chunk_base = ((size_t)b * TT + (size_t)c * CH) * HH;
    const float4* __restrict__ x4 = (const float4*)(x + chunk_base);
    float4* __restrict__ o4 = (float4*)(out + chunk_base);
    const __half* __restrict__ fp = g_f16 + chunk_base;

#pragma unroll 8
    for (int it = 0; it < CH / 8; ++it) {
        int row = it * 8 + 2 * r0;                 // rows row, row+1
        size_t vi0 = (size_t)row * (HH / 4) + hg;  // float4 index
        size_t vi1 = vi0 + (HH / 4);

        float4 xv0 = x4[vi0];
        float4 xv1 = x4[vi1];
        const __half2* fh0 = (const __half2*)(fp + 4 * vi0);
        const __half2* fh1 = (const __half2*)(fp + 4 * vi1);
        float2 a01 = __half22float2(fh0[0]);
        float2 a23 = __half22float2(fh0[1]);
        float2 b01 = __half22float2(fh1[0]);
        float2 b23 = __half22float2(fh1[1]);

        float4 ov0, ov1;
        ov0.x = fmaf(a01.x, A[0], xv0.x) + B[0];
        ov0.y = fmaf(a01.y, A[1], xv0.y) + B[1];
        ov0.z = fmaf(a23.x, A[2], xv0.z) + B[2];
        ov0.w = fmaf(a23.y, A[3], xv0.w) + B[3];
        ov1.x = fmaf(b01.x, A[0], xv1.x) + B[0];
        ov1.y = fmaf(b01.y, A[1], xv1.y) + B[1];
        ov1.z = fmaf(b23.x, A[2], xv1.z) + B[2];
        ov1.w = fmaf(b23.y, A[3], xv1.w) + B[3];
        __stcs(&o4[vi0], ov0);
        __stcs(&o4[vi1], ov1);
    }
}

extern "C" void kernel_launch(void* const* d_in, const int* in_sizes, int n_in,
                              void* d_out, int out_size) {
    (void)in_sizes; (void)n_in; (void)out_size;
    const float* x     = (const float*)d_in[0];
    const float* alpha = (const float*)d_in[1];
    const float* gamma = (const float*)d_in[2];
    const float* beta  = (const float*)d_in[3];
    float* out = (float*)d_out;

    fan_kernel<<<NBLK, HH>>>(x, alpha);
    stats_kernel<<<2 * HH, 256>>>(gamma, beta);
    apply_kernel<<<NBLK, 256>>>(x, out);
}

// round 15
// speedup vs baseline: 1.3499x; 1.0091x over previous
#include <cuda_runtime.h>
#include <cuda_fp16.h>
#include <math.h>

#define BB 64
#define TT 2048
#define HH 256
#define CH 128
#define NCHUNK 16              // TT / CH
#define NBLK (BB * NCHUNK)     // 1024
#define FAN_EPS 1e-4f

// Compile-time caps: 1e4 / sqrt(w-1)
#define CAP5  (1.0e4f / 2.0f)
#define CAP10 (1.0e4f / 3.0f)
#define CAP20 (1.0e4f / 4.35889894354067f)

// Transposed partial layout: [slice][h][blk] -> coalesced reduction reads.
__device__ float g_psum[2][HH][NBLK];
__device__ float g_psumsq[2][HH][NBLK];
__device__ float g_cA[2][HH];   // gamma/sd per slice
__device__ float g_cB[2][HH];   // beta - mu*gamma/sd per slice

// Packed per-element (x, f) in fp16: .x = x, .y = f. 128MB static scratch.
__device__ __half2 g_pack[(size_t)BB * TT * HH];

// mu and pre-scale clamped inverse-sd from UNSCALED variance varp = s2 - s1*mu:
//   r = min(rsqrt(varp), CAP) with CAP = 1e4/sqrt(w-1)  [immediate]
//   caller multiplies by alk = al*sqrt(w-1): exactly min(rsqrt(var),1e4)*al.
// No fmax(varp,0): varp<0 -> rsqrt=NaN -> fminf(NaN,CAP)=CAP; exact FMA
// cancellation yields +0 -> rsqrt=+inf -> CAP. Identical to the clamp.
__device__ __forceinline__ void wstat(float s1, float s2, float invw, float cap,
                                      float& mu, float& r) {
    mu = s1 * invw;
    float varp = fmaf(-s1, mu, s2);
    r = fminf(rsqrtf(varp), cap);
}

template <bool EDGE>
__device__ __forceinline__ void process_chunk(
    const float* __restrict__ px, __half2* __restrict__ pf, int t0,
    float alk5, float alk10, float alk20, float& accS, float& accQ)
{
    float hist[32];
    float s1_5 = 0, s2_5 = 0, s1_10 = 0, s2_10 = 0, s1_20 = 0, s2_20 = 0;
    float fmu5 = 0, fr5 = 0, fmu10 = 0, fr10 = 0, fmu20 = 0, fr20 = 0;

    if (EDGE) {
        // chunk 0: ring starts zeroed; first-full-window stats for edge pad.
#pragma unroll
        for (int j = 0; j < 32; j++) hist[j] = 0.0f;
        float s1 = 0, s2 = 0;
#pragma unroll
        for (int j = 0; j < 20; j++) {
            float v = px[j * HH];
            s1 += v; s2 = fmaf(v, v, s2);
            if (j == 4)  wstat(s1, s2, 0.2f,  CAP5,  fmu5,  fr5);
            if (j == 9)  wstat(s1, s2, 0.1f,  CAP10, fmu10, fr10);
            if (j == 19) wstat(s1, s2, 0.05f, CAP20, fmu20, fr20);
        }
    } else {
        // preload halo x[t0-32 .. t0-1]; t0 % 32 == 0 keeps ring phase aligned.
#pragma unroll
        for (int j = 0; j < 32; j++) hist[j] = px[(t0 - 32 + j) * HH];
#pragma unroll
        for (int j = 12; j < 32; j++) {
            float v = hist[j];
            s1_20 += v; s2_20 = fmaf(v, v, s2_20);
            if (j >= 22) { s1_10 += v; s2_10 = fmaf(v, v, s2_10); }
            if (j >= 27) { s1_5  += v; s2_5  = fmaf(v, v, s2_5);  }
        }
    }

    const float* p = px + (size_t)t0 * HH;
    __half2* pw = pf + (size_t)t0 * HH;

#pragma unroll 1
    for (int base = 0; base < CH; base += 32) {
#pragma unroll
        for (int u = 0; u < 32; ++u) {
            float xt  = p[u * HH];
            float x5  = hist[(u + 27) & 31];
            float x10 = hist[(u + 22) & 31];
            float x20 = hist[(u + 12) & 31];
            hist[u] = xt;
            // s1 += (xt-xw); s2 += (xt-xw)*(xt+xw)
            {
                float d = xt - x5,  q = xt + x5;
                s1_5  += d;  s2_5  = fmaf(d, q, s2_5);
            }
            {
                float d = xt - x10, q = xt + x10;
                s1_10 += d;  s2_10 = fmaf(d, q, s2_10);
            }
            {
                float d = xt - x20, q = xt + x20;
                s1_20 += d;  s2_20 = fmaf(d, q, s2_20);
            }

            float mu5, r5, mu10, r10, mu20, r20;
            wstat(s1_5,  s2_5,  0.2f,  CAP5,  mu5,  r5);
            wstat(s1_10, s2_10, 0.1f,  CAP10, mu10, r10);
            wstat(s1_20, s2_20, 0.05f, CAP20, mu20, r20);

            if (EDGE) {
                int t = base + u;          // t0 == 0 here
                if (t < 4)  { mu5  = fmu5;  r5  = fr5;  }
                if (t < 9)  { mu10 = fmu10; r10 = fr10; }
                if (t < 19) { mu20 = fmu20; r20 = fr20; }
            }

            float w5 = r5 * alk5, w10 = r10 * alk10, w20 = r20 * alk20;
            float wsum = (w5 + w10) + w20;
            float msum = fmaf(mu20, w20, fmaf(mu10, w10, mu5 * w5));
            float f = fmaf(xt, wsum, -msum);

            // one packed cvt + one STG.32: (.x = x, .y = f)
            pw[u * HH] = __floats2half2_rn(xt, f);
            accS += f;
            accQ = fmaf(f, f, accQ);
        }
        p  += 32 * HH;
        pw += 32 * HH;
    }
}

__global__ __launch_bounds__(HH, 4)
void fan_kernel(const float* __restrict__ x, const float* __restrict__ alpha) {
    const int c  = blockIdx.x & (NCHUNK - 1);
    const int b  = blockIdx.x >> 4;
    const int h  = threadIdx.x;
    const int t0 = c * CH;
    const float* px = x + ((size_t)b * TT) * HH + h;
    __half2* pf = g_pack + ((size_t)b * TT) * HH + h;

    // softmax over the 3 window weights; fold sqrt(w-1) in (3 live constants).
    float alk5, alk10, alk20;
    {
        float a0 = alpha[h * 3 + 0], a1 = alpha[h * 3 + 1], a2 = alpha[h * 3 + 2];
        float mx = fmaxf(a0, fmaxf(a1, a2));
        float e0 = expf(a0 - mx), e1 = expf(a1 - mx), e2 = expf(a2 - mx);
        float inv = 1.0f / (e0 + e1 + e2);
        alk5  = e0 * inv * 2.0f;              // sqrt(4)
        alk10 = e1 * inv * 3.0f;              // sqrt(9)
        alk20 = e2 * inv * 4.35889894354067f; // sqrt(19)
    }

    float accS = 0.0f, accQ = 0.0f;
    if (c == 0)
        process_chunk<true >(px, pf, t0, alk5, alk10, alk20, accS, accQ);
    else
        process_chunk<false>(px, pf, t0, alk5, alk10, alk20, accS, accQ);

    const int blk = blockIdx.x;
    const bool in0 = (c < 12);   // t < 1536
    const bool in1 = (c >= 8);   // t >= 1024
    g_psum[0][h][blk]   = in0 ? accS : 0.0f;
    g_psumsq[0][h][blk] = in0 ? accQ : 0.0f;
    g_psum[1][h][blk]   = in1 ? accS : 0.0f;
    g_psumsq[1][h][blk] = in1 ? accQ : 0.0f;
}

// One block per (slice, h): 256 threads tree-reduce the 1024 partials.
__global__ __launch_bounds__(256)
void stats_kernel(const float* __restrict__ gamma, const float* __restrict__ beta) {
    const int s = blockIdx.x >> 8;
    const int h = blockIdx.x & (HH - 1);
    const int tid = threadIdx.x;

    double dS = 0.0, dQ = 0.0;
#pragma unroll
    for (int i = 0; i < NBLK / 256; ++i) {
        dS += (double)g_psum[s][h][tid + i * 256];
        dQ += (double)g_psumsq[s][h][tid + i * 256];
    }
    __shared__ double shS[256], shQ[256];
    shS[tid] = dS; shQ[tid] = dQ;
    __syncthreads();
    for (int off = 128; off > 0; off >>= 1) {
        if (tid < off) { shS[tid] += shS[tid + off]; shQ[tid] += shQ[tid + off]; }
        __syncthreads();
    }
    if (tid == 0) {
        double S = shS[0], Q = shQ[0];
        const double n = (s == 0) ? (double)BB * 1536.0 : (double)BB * 1024.0;
        double mu  = S / n;
        double var = (Q - S * S / n) / (n - 1.0);
        if (var < 0.0) var = 0.0;
        double sd = sqrt(var);
        if (sd < 1e-4) sd = 1e-4;
        float g  = gamma[s * HH + h];
        float be = beta[s * HH + h];
        float a  = (float)((double)g / sd);
        g_cA[s][h] = a;
        g_cB[s][h] = be - (float)mu * a;
    }
}

// Streaming apply from the packed (x, f) buffer only:
//   out = x + cAr*f + cBr, region-folded coefficients.
// One LDG.128 per 4 elements, one STG.128 out. Blocks run in REVERSE order of
// fan's writes so reads start on the L2-resident tail of the pack buffer;
// __stcs on out keeps stores from evicting it.
__global__ __launch_bounds__(256)
void apply_kernel(float* __restrict__ out) {
    const int blk = (NBLK - 1) - (int)blockIdx.x;   // reversed traversal
    const int c   = blk & (NCHUNK - 1);
    const int b   = blk >> 4;
    const int tid = threadIdx.x;
    const int hg  = tid & 63;        // h-group: channels 4*hg .. 4*hg+3
    const int r0  = tid >> 6;        // row offset 0..3

    // Region is uniform per chunk (boundaries 1024/1536 multiples of CH).
    const float inv1 = 1.0f / (1.0f + FAN_EPS);
    const float inv2 = 1.0f / (2.0f + FAN_EPS);
    float A[4], B[4];
#pragma unroll
    for (int j = 0; j < 4; ++j) {
        int h = 4 * hg + j;
        float A0 = g_cA[0][h], B0 = g_cB[0][h];
        float A1 = g_cA[1][h], B1 = g_cB[1][h];
        if (c < 8)       { A[j] = A0 * inv1;        B[j] = B0 * inv1; }
        else if (c < 12) { A[j] = (A0 + A1) * inv2; B[j] = (B0 + B1) * inv2; }
        else             { A[j] = A1 * inv1;        B[j] = B1 * inv1; }
    }

    const size_t chunk_base = ((size_t)b * TT + (size_t)c * CH) * HH;
    const uint4* __restrict__ p4 = (const uint4*)(g_pack + chunk_base);
    float4* __restrict__ o4 = (float4*)(out + chunk_base);

#pragma unroll 8
    for (int it = 0; it < CH / 4; ++it) {
        int row = it * 4 + r0;
        size_t vi = (size_t)row * (HH / 4) + hg;   // 4-element vector index
        uint4 w = p4[vi];
        float2 e0 = __half22float2(*(const __half2*)&w.x);  // (x, f) ch 0
        float2 e1 = __half22float2(*(const __half2*)&w.y);
        float2 e2 = __half22float2(*(const __half2*)&w.z);
        float2 e3 = __half22float2(*(const __half2*)&w.w);
        float4 ov;
        ov.x = fmaf(e0.y, A[0], e0.x) + B[0];
        ov.y = fmaf(e1.y, A[1], e1.x) + B[1];
        ov.z = fmaf(e2.y, A[2], e2.x) + B[2];
        ov.w = fmaf(e3.y, A[3], e3.x) + B[3];
        __stcs(&o4[vi], ov);
    }
}

extern "C" void kernel_launch(void* const* d_in, const int* in_sizes, int n_in,
                              void* d_out, int out_size) {
    (void)in_sizes; (void)n_in; (void)out_size;
    const float* x     = (const float*)d_in[0];
    const float* alpha = (const float*)d_in[1];
    const float* gamma = (const float*)d_in[2];
    const float* beta  = (const float*)d_in[3];
    float* out = (float*)d_out;

    fan_kernel<<<NBLK, HH>>>(x, alpha);
    stats_kernel<<<2 * HH, 256>>>(gamma, beta);
    apply_kernel<<<NBLK, 256>>>(out);
}

// round 16
// speedup vs baseline: 1.3602x; 1.0077x over previous
#include <cuda_runtime.h>
#include <cuda_fp16.h>
#include <math.h>

#define BB 64
#define TT 2048
#define HH 256
#define CH 128
#define NCHUNK 16              // TT / CH
#define NBLK (BB * NCHUNK)     // 1024
#define FAN_EPS 1e-4f

// Compile-time caps: 1e4 / sqrt(w-1)
#define CAP5  (1.0e4f / 2.0f)
#define CAP10 (1.0e4f / 3.0f)
#define CAP20 (1.0e4f / 4.35889894354067f)

// Transposed partial layout: [slice][h][blk] -> coalesced reduction reads.
__device__ float g_psum[2][HH][NBLK];
__device__ float g_psumsq[2][HH][NBLK];
__device__ float g_cA[2][HH];   // gamma/sd per slice
__device__ float g_cB[2][HH];   // beta - mu*gamma/sd per slice

// Packed per-element (x, f) in fp16: .x = x, .y = f. 128MB static scratch.
__device__ __half2 g_pack[(size_t)BB * TT * HH];

// Invalidate a dirty L2 line WITHOUT writeback (write-once/read-once scratch).
__device__ __forceinline__ void discard_l2(const void* p) {
    asm volatile("discard.global.L2 [%0], 128;" :: "l"(p) : "memory");
}

// mu and pre-scale clamped inverse-sd from UNSCALED variance varp = s2 - s1*mu:
//   r = min(rsqrt(varp), CAP) with CAP = 1e4/sqrt(w-1)  [immediate]
//   caller multiplies by alk = al*sqrt(w-1): exactly min(rsqrt(var),1e4)*al.
// No fmax(varp,0): varp<0 -> rsqrt=NaN -> fminf(NaN,CAP)=CAP; exact FMA
// cancellation yields +0 -> rsqrt=+inf -> CAP. Identical to the clamp.
__device__ __forceinline__ void wstat(float s1, float s2, float invw, float cap,
                                      float& mu, float& r) {
    mu = s1 * invw;
    float varp = fmaf(-s1, mu, s2);
    r = fminf(rsqrtf(varp), cap);
}

template <bool EDGE>
__device__ __forceinline__ void process_chunk(
    const float* __restrict__ px, __half2* __restrict__ pf, int t0,
    float alk5, float alk10, float alk20, float& accS, float& accQ)
{
    float hist[32];
    float s1_5 = 0, s2_5 = 0, s1_10 = 0, s2_10 = 0, s1_20 = 0, s2_20 = 0;
    float fmu5 = 0, fr5 = 0, fmu10 = 0, fr10 = 0, fmu20 = 0, fr20 = 0;

    if (EDGE) {
        // chunk 0: ring starts zeroed; first-full-window stats for edge pad.
#pragma unroll
        for (int j = 0; j < 32; j++) hist[j] = 0.0f;
        float s1 = 0, s2 = 0;
#pragma unroll
        for (int j = 0; j < 20; j++) {
            float v = px[j * HH];
            s1 += v; s2 = fmaf(v, v, s2);
            if (j == 4)  wstat(s1, s2, 0.2f,  CAP5,  fmu5,  fr5);
            if (j == 9)  wstat(s1, s2, 0.1f,  CAP10, fmu10, fr10);
            if (j == 19) wstat(s1, s2, 0.05f, CAP20, fmu20, fr20);
        }
    } else {
        // preload halo x[t0-32 .. t0-1]; t0 % 32 == 0 keeps ring phase aligned.
#pragma unroll
        for (int j = 0; j < 32; j++) hist[j] = px[(t0 - 32 + j) * HH];
#pragma unroll
        for (int j = 12; j < 32; j++) {
            float v = hist[j];
            s1_20 += v; s2_20 = fmaf(v, v, s2_20);
            if (j >= 22) { s1_10 += v; s2_10 = fmaf(v, v, s2_10); }
            if (j >= 27) { s1_5  += v; s2_5  = fmaf(v, v, s2_5);  }
        }
    }

    const float* p = px + (size_t)t0 * HH;
    __half2* pw = pf + (size_t)t0 * HH;

#pragma unroll 1
    for (int base = 0; base < CH; base += 32) {
#pragma unroll
        for (int u = 0; u < 32; ++u) {
            float xt  = p[u * HH];
            float x5  = hist[(u + 27) & 31];
            float x10 = hist[(u + 22) & 31];
            float x20 = hist[(u + 12) & 31];
            hist[u] = xt;
            // s1 += (xt-xw); s2 += (xt-xw)*(xt+xw)
            {
                float d = xt - x5,  q = xt + x5;
                s1_5  += d;  s2_5  = fmaf(d, q, s2_5);
            }
            {
                float d = xt - x10, q = xt + x10;
                s1_10 += d;  s2_10 = fmaf(d, q, s2_10);
            }
            {
                float d = xt - x20, q = xt + x20;
                s1_20 += d;  s2_20 = fmaf(d, q, s2_20);
            }

            float mu5, r5, mu10, r10, mu20, r20;
            wstat(s1_5,  s2_5,  0.2f,  CAP5,  mu5,  r5);
            wstat(s1_10, s2_10, 0.1f,  CAP10, mu10, r10);
            wstat(s1_20, s2_20, 0.05f, CAP20, mu20, r20);

            if (EDGE) {
                int t = base + u;          // t0 == 0 here
                if (t < 4)  { mu5  = fmu5;  r5  = fr5;  }
                if (t < 9)  { mu10 = fmu10; r10 = fr10; }
                if (t < 19) { mu20 = fmu20; r20 = fr20; }
            }

            float w5 = r5 * alk5, w10 = r10 * alk10, w20 = r20 * alk20;
            float wsum = (w5 + w10) + w20;
            float msum = fmaf(mu20, w20, fmaf(mu10, w10, mu5 * w5));
            float f = fmaf(xt, wsum, -msum);

            // one packed cvt + one STG.32: (.x = x, .y = f)
            pw[u * HH] = __floats2half2_rn(xt, f);
            accS += f;
            accQ = fmaf(f, f, accQ);
        }
        p  += 32 * HH;
        pw += 32 * HH;
    }
}

__global__ __launch_bounds__(HH, 4)
void fan_kernel(const float* __restrict__ x, const float* __restrict__ alpha) {
    const int c  = blockIdx.x & (NCHUNK - 1);
    const int b  = blockIdx.x >> 4;
    const int h  = threadIdx.x;
    const int t0 = c * CH;
    const float* px = x + ((size_t)b * TT) * HH + h;
    __half2* pf = g_pack + ((size_t)b * TT) * HH + h;

    // softmax over the 3 window weights; fold sqrt(w-1) in (3 live constants).
    float alk5, alk10, alk20;
    {
        float a0 = alpha[h * 3 + 0], a1 = alpha[h * 3 + 1], a2 = alpha[h * 3 + 2];
        float mx = fmaxf(a0, fmaxf(a1, a2));
        float e0 = expf(a0 - mx), e1 = expf(a1 - mx), e2 = expf(a2 - mx);
        float inv = 1.0f / (e0 + e1 + e2);
        alk5  = e0 * inv * 2.0f;              // sqrt(4)
        alk10 = e1 * inv * 3.0f;              // sqrt(9)
        alk20 = e2 * inv * 4.35889894354067f; // sqrt(19)
    }

    float accS = 0.0f, accQ = 0.0f;
    if (c == 0)
        process_chunk<true >(px, pf, t0, alk5, alk10, alk20, accS, accQ);
    else
        process_chunk<false>(px, pf, t0, alk5, alk10, alk20, accS, accQ);

    const int blk = blockIdx.x;
    const bool in0 = (c < 12);   // t < 1536
    const bool in1 = (c >= 8);   // t >= 1024
    g_psum[0][h][blk]   = in0 ? accS : 0.0f;
    g_psumsq[0][h][blk] = in0 ? accQ : 0.0f;
    g_psum[1][h][blk]   = in1 ? accS : 0.0f;
    g_psumsq[1][h][blk] = in1 ? accQ : 0.0f;
}

// One block per (slice, h): 256 threads tree-reduce the 1024 partials.
__global__ __launch_bounds__(256)
void stats_kernel(const float* __restrict__ gamma, const float* __restrict__ beta) {
    const int s = blockIdx.x >> 8;
    const int h = blockIdx.x & (HH - 1);
    const int tid = threadIdx.x;

    double dS = 0.0, dQ = 0.0;
#pragma unroll
    for (int i = 0; i < NBLK / 256; ++i) {
        dS += (double)g_psum[s][h][tid + i * 256];
        dQ += (double)g_psumsq[s][h][tid + i * 256];
    }
    __shared__ double shS[256], shQ[256];
    shS[tid] = dS; shQ[tid] = dQ;
    __syncthreads();
    for (int off = 128; off > 0; off >>= 1) {
        if (tid < off) { shS[tid] += shS[tid + off]; shQ[tid] += shQ[tid + off]; }
        __syncthreads();
    }
    if (tid == 0) {
        double S = shS[0], Q = shQ[0];
        const double n = (s == 0) ? (double)BB * 1536.0 : (double)BB * 1024.0;
        double mu  = S / n;
        double var = (Q - S * S / n) / (n - 1.0);
        if (var < 0.0) var = 0.0;
        double sd = sqrt(var);
        if (sd < 1e-4) sd = 1e-4;
        float g  = gamma[s * HH + h];
        float be = beta[s * HH + h];
        float a  = (float)((double)g / sd);
        g_cA[s][h] = a;
        g_cB[s][h] = be - (float)mu * a;
    }
}

// Streaming apply from the packed (x, f) buffer only:
//   out = x + cAr*f + cBr, region-folded coefficients.
// One LDG.128 per 4 elements, one STG.128 out. Blocks run in REVERSE order of
// fan's writes so reads start on the L2-resident tail of the pack buffer;
// __stcs on out keeps stores from evicting it. After the loop, each warp
// DISCARDS the pack lines it consumed (write-once scratch) so dirty L2 lines
// are never written back to DRAM.
__global__ __launch_bounds__(256)
void apply_kernel(float* __restrict__ out) {
    const int blk = (NBLK - 1) - (int)blockIdx.x;   // reversed traversal
    const int c   = blk & (NCHUNK - 1);
    const int b   = blk >> 4;
    const int tid = threadIdx.x;
    const int hg  = tid & 63;        // h-group: channels 4*hg .. 4*hg+3
    const int r0  = tid >> 6;        // row offset 0..3

    // Region is uniform per chunk (boundaries 1024/1536 multiples of CH).
    const float inv1 = 1.0f / (1.0f + FAN_EPS);
    const float inv2 = 1.0f / (2.0f + FAN_EPS);
    float A[4], B[4];
#pragma unroll
    for (int j = 0; j < 4; ++j) {
        int h = 4 * hg + j;
        float A0 = g_cA[0][h], B0 = g_cB[0][h];
        float A1 = g_cA[1][h], B1 = g_cB[1][h];
        if (c < 8)       { A[j] = A0 * inv1;        B[j] = B0 * inv1; }
        else if (c < 12) { A[j] = (A0 + A1) * inv2; B[j] = (B0 + B1) * inv2; }
        else             { A[j] = A1 * inv1;        B[j] = B1 * inv1; }
    }

    const size_t chunk_base = ((size_t)b * TT + (size_t)c * CH) * HH;
    const uint4* __restrict__ p4 = (const uint4*)(g_pack + chunk_base);
    float4* __restrict__ o4 = (float4*)(out + chunk_base);

#pragma unroll 8
    for (int it = 0; it < CH / 4; ++it) {
        int row = it * 4 + r0;
        size_t vi = (size_t)row * (HH / 4) + hg;   // 4-element vector index
        uint4 w = p4[vi];
        float2 e0 = __half22float2(*(const __half2*)&w.x);  // (x, f) ch 0
        float2 e1 = __half22float2(*(const __half2*)&w.y);
        float2 e2 = __half22float2(*(const __half2*)&w.z);
        float2 e3 = __half22float2(*(const __half2*)&w.w);
        float4 ov;
        ov.x = fmaf(e0.y, A[0], e0.x) + B[0];
        ov.y = fmaf(e1.y, A[1], e1.x) + B[1];
        ov.z = fmaf(e2.y, A[2], e2.x) + B[2];
        ov.w = fmaf(e3.y, A[3], e3.x) + B[3];
        __stcs(&o4[vi], ov);
    }

    // All lanes have consumed their loads (register deps force completion);
    // sync the warp, then one leader per 128B line discards it.
    __syncwarp();
    if ((tid & 7) == 0) {
#pragma unroll
        for (int it = 0; it < CH / 4; ++it) {
            int row = it * 4 + r0;
            size_t vi = (size_t)row * (HH / 4) + hg;
            discard_l2(&p4[vi]);    // 128B line: this thread's + next 7 lanes'
        }
    }
}

extern "C" void kernel_launch(void* const* d_in, const int* in_sizes, int n_in,
                              void* d_out, int out_size) {
    (void)in_sizes; (void)n_in; (void)out_size;
    const float* x     = (const float*)d_in[0];
    const float* alpha = (const float*)d_in[1];
    const float* gamma = (const float*)d_in[2];
    const float* beta  = (const float*)d_in[3];
    float* out = (float*)d_out;

    fan_kernel<<<NBLK, HH>>>(x, alpha);
    stats_kernel<<<2 * HH, 256>>>(gamma, beta);
    apply_kernel<<<NBLK, 256>>>(out);
}

// round 17
// speedup vs baseline: 1.4545x; 1.0693x over previous
#include <cuda_runtime.h>
#include <cuda_fp16.h>
#include <math.h>

#define BB 64
#define TT 2048
#define HH 256
#define CH 128
#define NCHUNK 16              // TT / CH
#define NBLK (BB * NCHUNK)     // 1024
#define FAN_EPS 1e-4f

// Apply-side geometry: 64-row subchunks, 2048 blocks.
#define ACH 64
#define ANCHUNK (TT / ACH)     // 32
#define ANBLK (BB * ANCHUNK)   // 2048

// Compile-time caps: 1e4 / sqrt(w-1)
#define CAP5  (1.0e4f / 2.0f)
#define CAP10 (1.0e4f / 3.0f)
#define CAP20 (1.0e4f / 4.35889894354067f)

// Transposed partial layout: [slice][h][blk] -> coalesced reduction reads.
__device__ float g_psum[2][HH][NBLK];
__device__ float g_psumsq[2][HH][NBLK];
__device__ float g_cA[2][HH];   // gamma/sd per slice
__device__ float g_cB[2][HH];   // beta - mu*gamma/sd per slice

// Packed per-element (x, f) in fp16: .x = x, .y = f. 128MB static scratch.
__device__ __half2 g_pack[(size_t)BB * TT * HH];

// Invalidate a dirty L2 line WITHOUT writeback (write-once/read-once scratch).
__device__ __forceinline__ void discard_l2(const void* p) {
    asm volatile("discard.global.L2 [%0], 128;" :: "l"(p) : "memory");
}

// mu and pre-scale clamped inverse-sd from UNSCALED variance varp = s2 - s1*mu:
//   r = min(rsqrt(varp), CAP) with CAP = 1e4/sqrt(w-1)  [immediate]
//   caller multiplies by alk = al*sqrt(w-1): exactly min(rsqrt(var),1e4)*al.
// No fmax(varp,0): varp<0 -> rsqrt=NaN -> fminf(NaN,CAP)=CAP; exact FMA
// cancellation yields +0 -> rsqrt=+inf -> CAP. Identical to the clamp.
__device__ __forceinline__ void wstat(float s1, float s2, float invw, float cap,
                                      float& mu, float& r) {
    mu = s1 * invw;
    float varp = fmaf(-s1, mu, s2);
    r = fminf(rsqrtf(varp), cap);
}

template <bool EDGE>
__device__ __forceinline__ void process_chunk(
    const float* __restrict__ px, __half2* __restrict__ pf, int t0,
    float alk5, float alk10, float alk20, float& accS, float& accQ)
{
    float hist[32];
    float s1_5 = 0, s2_5 = 0, s1_10 = 0, s2_10 = 0, s1_20 = 0, s2_20 = 0;
    float fmu5 = 0, fr5 = 0, fmu10 = 0, fr10 = 0, fmu20 = 0, fr20 = 0;

    if (EDGE) {
        // chunk 0: ring starts zeroed; first-full-window stats for edge pad.
#pragma unroll
        for (int j = 0; j < 32; j++) hist[j] = 0.0f;
        float s1 = 0, s2 = 0;
#pragma unroll
        for (int j = 0; j < 20; j++) {
            float v = px[j * HH];
            s1 += v; s2 = fmaf(v, v, s2);
            if (j == 4)  wstat(s1, s2, 0.2f,  CAP5,  fmu5,  fr5);
            if (j == 9)  wstat(s1, s2, 0.1f,  CAP10, fmu10, fr10);
            if (j == 19) wstat(s1, s2, 0.05f, CAP20, fmu20, fr20);
        }
    } else {
        // preload halo x[t0-32 .. t0-1]; t0 % 32 == 0 keeps ring phase aligned.
#pragma unroll
        for (int j = 0; j < 32; j++) hist[j] = px[(t0 - 32 + j) * HH];
#pragma unroll
        for (int j = 12; j < 32; j++) {
            float v = hist[j];
            s1_20 += v; s2_20 = fmaf(v, v, s2_20);
            if (j >= 22) { s1_10 += v; s2_10 = fmaf(v, v, s2_10); }
            if (j >= 27) { s1_5  += v; s2_5  = fmaf(v, v, s2_5);  }
        }
    }

    const float* p = px + (size_t)t0 * HH;
    __half2* pw = pf + (size_t)t0 * HH;

#pragma unroll 1
    for (int base = 0; base < CH; base += 32) {
#pragma unroll
        for (int u = 0; u < 32; ++u) {
            float xt  = p[u * HH];
            float x5  = hist[(u + 27) & 31];
            float x10 = hist[(u + 22) & 31];
            float x20 = hist[(u + 12) & 31];
            hist[u] = xt;
            // s1 += (xt-xw); s2 += (xt-xw)*(xt+xw)
            {
                float d = xt - x5,  q = xt + x5;
                s1_5  += d;  s2_5  = fmaf(d, q, s2_5);
            }
            {
                float d = xt - x10, q = xt + x10;
                s1_10 += d;  s2_10 = fmaf(d, q, s2_10);
            }
            {
                float d = xt - x20, q = xt + x20;
                s1_20 += d;  s2_20 = fmaf(d, q, s2_20);
            }

            float mu5, r5, mu10, r10, mu20, r20;
            wstat(s1_5,  s2_5,  0.2f,  CAP5,  mu5,  r5);
            wstat(s1_10, s2_10, 0.1f,  CAP10, mu10, r10);
            wstat(s1_20, s2_20, 0.05f, CAP20, mu20, r20);

            if (EDGE) {
                int t = base + u;          // t0 == 0 here
                if (t < 4)  { mu5  = fmu5;  r5  = fr5;  }
                if (t < 9)  { mu10 = fmu10; r10 = fr10; }
                if (t < 19) { mu20 = fmu20; r20 = fr20; }
            }

            float w5 = r5 * alk5, w10 = r10 * alk10, w20 = r20 * alk20;
            float wsum = (w5 + w10) + w20;
            float msum = fmaf(mu20, w20, fmaf(mu10, w10, mu5 * w5));
            float f = fmaf(xt, wsum, -msum);

            // one packed cvt + one STG.32: (.x = x, .y = f)
            pw[u * HH] = __floats2half2_rn(xt, f);
            accS += f;
            accQ = fmaf(f, f, accQ);
        }
        p  += 32 * HH;
        pw += 32 * HH;
    }
}

__global__ __launch_bounds__(HH, 4)
void fan_kernel(const float* __restrict__ x, const float* __restrict__ alpha) {
    const int c  = blockIdx.x & (NCHUNK - 1);
    const int b  = blockIdx.x >> 4;
    const int h  = threadIdx.x;
    const int t0 = c * CH;
    const float* px = x + ((size_t)b * TT) * HH + h;
    __half2* pf = g_pack + ((size_t)b * TT) * HH + h;

    // softmax over the 3 window weights; fold sqrt(w-1) in (3 live constants).
    float alk5, alk10, alk20;
    {
        float a0 = alpha[h * 3 + 0], a1 = alpha[h * 3 + 1], a2 = alpha[h * 3 + 2];
        float mx = fmaxf(a0, fmaxf(a1, a2));
        float e0 = expf(a0 - mx), e1 = expf(a1 - mx), e2 = expf(a2 - mx);
        float inv = 1.0f / (e0 + e1 + e2);
        alk5  = e0 * inv * 2.0f;              // sqrt(4)
        alk10 = e1 * inv * 3.0f;              // sqrt(9)
        alk20 = e2 * inv * 4.35889894354067f; // sqrt(19)
    }

    float accS = 0.0f, accQ = 0.0f;
    if (c == 0)
        process_chunk<true >(px, pf, t0, alk5, alk10, alk20, accS, accQ);
    else
        process_chunk<false>(px, pf, t0, alk5, alk10, alk20, accS, accQ);

    const int blk = blockIdx.x;
    const bool in0 = (c < 12);   // t < 1536
    const bool in1 = (c >= 8);   // t >= 1024
    g_psum[0][h][blk]   = in0 ? accS : 0.0f;
    g_psumsq[0][h][blk] = in0 ? accQ : 0.0f;
    g_psum[1][h][blk]   = in1 ? accS : 0.0f;
    g_psumsq[1][h][blk] = in1 ? accQ : 0.0f;
}

// One block per (slice, h): 256 threads tree-reduce the 1024 partials.
__global__ __launch_bounds__(256)
void stats_kernel(const float* __restrict__ gamma, const float* __restrict__ beta) {
    const int s = blockIdx.x >> 8;
    const int h = blockIdx.x & (HH - 1);
    const int tid = threadIdx.x;

    double dS = 0.0, dQ = 0.0;
#pragma unroll
    for (int i = 0; i < NBLK / 256; ++i) {
        dS += (double)g_psum[s][h][tid + i * 256];
        dQ += (double)g_psumsq[s][h][tid + i * 256];
    }
    __shared__ double shS[256], shQ[256];
    shS[tid] = dS; shQ[tid] = dQ;
    __syncthreads();
    for (int off = 128; off > 0; off >>= 1) {
        if (tid < off) { shS[tid] += shS[tid + off]; shQ[tid] += shQ[tid + off]; }
        __syncthreads();
    }
    if (tid == 0) {
        double S = shS[0], Q = shQ[0];
        const double n = (s == 0) ? (double)BB * 1536.0 : (double)BB * 1024.0;
        double mu  = S / n;
        double var = (Q - S * S / n) / (n - 1.0);
        if (var < 0.0) var = 0.0;
        double sd = sqrt(var);
        if (sd < 1e-4) sd = 1e-4;
        float g  = gamma[s * HH + h];
        float be = beta[s * HH + h];
        float a  = (float)((double)g / sd);
        g_cA[s][h] = a;
        g_cB[s][h] = be - (float)mu * a;
    }
}

// Streaming apply from the packed (x, f) buffer only:
//   out = x + cAr*f + cBr, region-folded coefficients.
// 2048 blocks of 64 rows (finer wave granularity), reversed traversal so reads
// start on the L2-resident tail of the pack buffer. Loads batched 4-deep for
// MLP; __stcs on out; consumed pack lines discarded (no DRAM writeback).
__global__ __launch_bounds__(256)
void apply_kernel(float* __restrict__ out) {
    const int blk = (ANBLK - 1) - (int)blockIdx.x;   // reversed traversal
    const int c   = blk & (ANCHUNK - 1);             // 64-row subchunk
    const int b   = blk >> 5;                        // log2(ANCHUNK)
    const int tid = threadIdx.x;
    const int hg  = tid & 63;        // h-group: channels 4*hg .. 4*hg+3
    const int r0  = tid >> 6;        // row offset 0..3
    const int t0  = c * ACH;

    // Region is uniform per subchunk (boundaries 1024/1536 multiples of ACH).
    const float inv1 = 1.0f / (1.0f + FAN_EPS);
    const float inv2 = 1.0f / (2.0f + FAN_EPS);
    float A[4], B[4];
#pragma unroll
    for (int j = 0; j < 4; ++j) {
        int h = 4 * hg + j;
        float A0 = g_cA[0][h], B0 = g_cB[0][h];
        float A1 = g_cA[1][h], B1 = g_cB[1][h];
        if (t0 < 1024)      { A[j] = A0 * inv1;        B[j] = B0 * inv1; }
        else if (t0 < 1536) { A[j] = (A0 + A1) * inv2; B[j] = (B0 + B1) * inv2; }
        else                { A[j] = A1 * inv1;        B[j] = B1 * inv1; }
    }

    const size_t chunk_base = ((size_t)b * TT + (size_t)t0) * HH;
    const uint4* __restrict__ p4 = (const uint4*)(g_pack + chunk_base);
    float4* __restrict__ o4 = (float4*)(out + chunk_base);

    // 64 rows / 4 rows-in-flight = 16 iterations, batched 4-deep.
#pragma unroll
    for (int o = 0; o < 4; ++o) {
        uint4 w[4];
        size_t vis[4];
#pragma unroll
        for (int k = 0; k < 4; ++k) {
            int row = o * 16 + k * 4 + r0;
            vis[k] = (size_t)row * (HH / 4) + hg;
            w[k] = p4[vis[k]];
        }
#pragma unroll
        for (int k = 0; k < 4; ++k) {
            float2 e0 = __half22float2(*(const __half2*)&w[k].x);  // (x, f)
            float2 e1 = __half22float2(*(const __half2*)&w[k].y);
            float2 e2 = __half22float2(*(const __half2*)&w[k].z);
            float2 e3 = __half22float2(*(const __half2*)&w[k].w);
            float4 ov;
            ov.x = fmaf(e0.y, A[0], e0.x) + B[0];
            ov.y = fmaf(e1.y, A[1], e1.x) + B[1];
            ov.z = fmaf(e2.y, A[2], e2.x) + B[2];
            ov.w = fmaf(e3.y, A[3], e3.x) + B[3];
            __stcs(&o4[vis[k]], ov);
        }
    }

    // All lanes have consumed their loads; one leader per 128B line discards.
    __syncwarp();
    if ((tid & 7) == 0) {
#pragma unroll
        for (int it = 0; it < ACH / 4; ++it) {
            int row = it * 4 + r0;
            size_t vi = (size_t)row * (HH / 4) + hg;
            discard_l2(&p4[vi]);    // 128B line: this thread's + next 7 lanes'
        }
    }
}

extern "C" void kernel_launch(void* const* d_in, const int* in_sizes, int n_in,
                              void* d_out, int out_size) {
    (void)in_sizes; (void)n_in; (void)out_size;
    const float* x     = (const float*)d_in[0];
    const float* alpha = (const float*)d_in[1];
    const float* gamma = (const float*)d_in[2];
    const float* beta  = (const float*)d_in[3];
    float* out = (float*)d_out;

    fan_kernel<<<NBLK, HH>>>(x, alpha);
    stats_kernel<<<2 * HH, 256>>>(gamma, beta);
    apply_kernel<<<ANBLK, 256>>>(out);
}